// round 8
// baseline (speedup 1.0000x reference)
#include <cuda_runtime.h>
#include <math.h>

// Blur_22754736735026: upfirdn2d, UP=2, DOWN=1, 4x4 kernel, pad (1,2).
// imgs: (16,128,128,128) f32 NCHW -> out: (16,128,255,255) f32.
//
// out(2i+py, 2j+px) = 2x2 weighted sum of in(i..i+1, j..j+1):
//   even out rows: kernel rows 1,3 ; odd rows: kernel rows 0,2
//   even out cols: kernel cols 1,3 ; odd cols: kernel cols 0,2
// Odd output row 2i+1 exists iff i < 127 (OH=255).
//
// Per output row-pair [g0, g0+510): row0 at g0 (align s=g0&3), row1 at g0+255
// (align (s+3)&3). Exactly one row is even-aligned -> stored DIRECTLY from
// registers via STG.128 (col-shift sigma in {0,2}); the other row goes through
// smem staging + coalesced scalar drain.

#define HB   128
#define WB   128

// ---- direct vector store of one 255-col row from registers ----------------
// v[8] = lane's cols 8l..8l+7. dbase is the global float index of col 0,
// dbase % 4 == sigma (sigma in {0,2}, warp-uniform).
__device__ __forceinline__ void direct_store(float* __restrict__ out,
                                             unsigned dbase, int sigma,
                                             const float v[8], int lane)
{
    if (sigma == 0) {
        float4* p = (float4*)(out + dbase + 8*lane);
        p[0] = make_float4(v[0], v[1], v[2], v[3]);
        if (lane < 31) {
            p[1] = make_float4(v[4], v[5], v[6], v[7]);
        } else {                                   // cols 252..254 only
            ((float2*)(out + dbase + 252))[0] = make_float2(v[4], v[5]);
            out[dbase + 254] = v[6];
        }
    } else {                                       // sigma == 2
        const float s0 = __shfl_down_sync(0xffffffffu, v[0], 1);
        const float s1 = __shfl_down_sync(0xffffffffu, v[1], 1);
        float4* p = (float4*)(out + dbase + 8*lane + 2);
        p[0] = make_float4(v[2], v[3], v[4], v[5]);
        if (lane < 31) {
            p[1] = make_float4(v[6], v[7], s0, s1);
        } else {                                   // lane31: cols 250..253 done, 254 scalar
            out[dbase + 254] = v[6];
        }
        if (lane == 0) {                           // head cols 0,1
            out[dbase + 0] = v[0];
            out[dbase + 1] = v[1];
        }
    }
}

// ---- smem stage + coalesced scalar drain of one 255-col row ----------------
__device__ __forceinline__ void smem_store(float* __restrict__ out,
                                           unsigned sbase, float* S,
                                           const float v[8], int lane)
{
    ((float4*)S)[2*lane    ] = make_float4(v[0], v[1], v[2], v[3]);
    ((float4*)S)[2*lane + 1] = make_float4(v[4], v[5], v[6], v[7]);
    __syncwarp();
    #pragma unroll
    for (int u = 0; u < 8; ++u) {
        const int c = lane + 32*u;
        if (u < 7 || lane < 31) out[sbase + c] = S[c];
    }
    __syncwarp();                                  // WAR before next reuse
}

// ---- compute one pair (input rows X,Y) -> ev/od and dispatch stores --------
__device__ __forceinline__ void do_pair(float* __restrict__ out,
                                        unsigned g0, bool row1_exists,
                                        const float4& X, float nX,
                                        const float4& Y, float nY,
                                        const float* kw,    // k00..k33 in regs
                                        float* S, int lane)
{
    const float ta[5] = { X.x, X.y, X.z, X.w, nX };
    const float tb[5] = { Y.x, Y.y, Y.z, Y.w, nY };
    float ev[8], od[8];
    #pragma unroll
    for (int u = 0; u < 4; ++u) {
        const float A = ta[u], B = ta[u+1], Cv = tb[u], D = tb[u+1];
        ev[2*u+0] = kw[5]*A + kw[7]*B + kw[13]*Cv + kw[15]*D;  // k11,k13,k31,k33
        ev[2*u+1] = kw[4]*A + kw[6]*B + kw[12]*Cv + kw[14]*D;  // k10,k12,k30,k32
        od[2*u+0] = kw[1]*A + kw[3]*B + kw[ 9]*Cv + kw[11]*D;  // k01,k03,k21,k23
        od[2*u+1] = kw[0]*A + kw[2]*B + kw[ 8]*Cv + kw[10]*D;  // k00,k02,k20,k22
    }

    const unsigned s    = g0 & 3u;
    const int     sigma = (s & 2u) ? 2 : 0;
    if (s & 1u) {                                  // row1 even-aligned
        if (row1_exists) direct_store(out, g0 + 255u, sigma, od, lane);
        smem_store(out, g0, S, ev, lane);
    } else {                                       // row0 even-aligned
        direct_store(out, g0, sigma, ev, lane);
        if (row1_exists) smem_store(out, g0 + 255u, S, od, lane);
    }
}

// ---------------- specialized: shapes known ---------------------------------
__global__ __launch_bounds__(256, 7)
void blur_spec3(const float4* __restrict__ in4,
                const float4* __restrict__ ker4,
                float* __restrict__ out)
{
    __shared__ float sm[8][256];

    const int lane = threadIdx.x & 31;
    const int w    = threadIdx.x >> 5;
    const unsigned task = blockIdx.x * 8u + w;     // 131072 tasks
    const unsigned t    = task & 63u;              // row-pair index in plane
    const unsigned img  = task >> 6;
    const unsigned i0   = 2u * t;

    float kw[16];
    {
        const float4 a = __ldg(ker4 + 0), b = __ldg(ker4 + 1),
                     c = __ldg(ker4 + 2), d = __ldg(ker4 + 3);
        kw[ 0]=a.x; kw[ 1]=a.y; kw[ 2]=a.z; kw[ 3]=a.w;
        kw[ 4]=b.x; kw[ 5]=b.y; kw[ 6]=b.z; kw[ 7]=b.w;
        kw[ 8]=c.x; kw[ 9]=c.y; kw[10]=c.z; kw[11]=c.w;
        kw[12]=d.x; kw[13]=d.y; kw[14]=d.z; kw[15]=d.w;
    }

    const unsigned rowbase = (img * HB + i0) * 32u + lane;
    const bool lastpair = (t == 63u);              // warp-uniform

    float4 r0 = in4[rowbase];
    float4 r1 = in4[rowbase + 32u];
    float4 r2 = make_float4(0.f, 0.f, 0.f, 0.f);
    if (!lastpair) r2 = in4[rowbase + 64u];

    float n0 = __shfl_down_sync(0xffffffffu, r0.x, 1);
    float n1 = __shfl_down_sync(0xffffffffu, r1.x, 1);
    float n2 = __shfl_down_sync(0xffffffffu, r2.x, 1);
    if (lane == 31) { n0 = 0.f; n1 = 0.f; n2 = 0.f; }

    float* S = sm[w];
    const unsigned g0A = img * 65025u + i0 * 510u;

    // pair A: input rows i0,i0+1 -> out rows 2i0, 2i0+1 (both always exist)
    do_pair(out, g0A,        true,      r0, n0, r1, n1, kw, S, lane);
    // pair B: input rows i0+1,i0+2 -> out rows 2i0+2, 2i0+3 (odd absent at t=63)
    do_pair(out, g0A + 510u, !lastpair, r1, n1, r2, n2, kw, S, lane);
}

// ---------------- generic guarded fallback (any shape) ----------------------
__global__ __launch_bounds__(256)
void blur_generic(const float* __restrict__ in,
                  const float* __restrict__ ker,
                  float* __restrict__ out,
                  int ntask, long long n_in_elems,
                  int OH, int OW, long long n_out_elems)
{
    __shared__ float sm[8][2][256];

    const int lane = threadIdx.x & 31;
    const int w    = threadIdx.x >> 5;
    const int task = blockIdx.x * 8 + w;
    if (task >= ntask) return;
    const int i    = task & (HB - 1);
    const int img  = task >> 7;

    float k00,k01,k02,k03,k10,k11,k12,k13,k20,k21,k22,k23,k30,k31,k32,k33;
    if (ker != nullptr) {
        k00 = __ldg(ker+ 0); k01 = __ldg(ker+ 1); k02 = __ldg(ker+ 2); k03 = __ldg(ker+ 3);
        k10 = __ldg(ker+ 4); k11 = __ldg(ker+ 5); k12 = __ldg(ker+ 6); k13 = __ldg(ker+ 7);
        k20 = __ldg(ker+ 8); k21 = __ldg(ker+ 9); k22 = __ldg(ker+10); k23 = __ldg(ker+11);
        k30 = __ldg(ker+12); k31 = __ldg(ker+13); k32 = __ldg(ker+14); k33 = __ldg(ker+15);
    } else {
        const float b0 = 0.125f, b1 = 0.375f;
        k00=b0*b0; k01=b0*b1; k02=b0*b1; k03=b0*b0;
        k10=b1*b0; k11=b1*b1; k12=b1*b1; k13=b1*b0;
        k20=b1*b0; k21=b1*b1; k22=b1*b1; k23=b1*b0;
        k30=b0*b0; k31=b0*b1; k32=b0*b1; k33=b0*b0;
    }

    const long long idx0 = ((long long)img * HB + i) * WB + lane * 4;
    float4 r0 = make_float4(0.f,0.f,0.f,0.f);
    float4 r1 = make_float4(0.f,0.f,0.f,0.f);
    if (idx0 + 3 < n_in_elems) r0 = *(const float4*)(in + idx0);
    if (i + 1 < HB && idx0 + WB + 3 < n_in_elems) r1 = *(const float4*)(in + idx0 + WB);

    float n0 = __shfl_down_sync(0xffffffffu, r0.x, 1);
    float n1 = __shfl_down_sync(0xffffffffu, r1.x, 1);
    if (lane == 31) { n0 = 0.f; n1 = 0.f; }

    const float ta[5] = { r0.x, r0.y, r0.z, r0.w, n0 };
    const float tb[5] = { r1.x, r1.y, r1.z, r1.w, n1 };

    float ev[8], od[8];
    #pragma unroll
    for (int u = 0; u < 4; ++u) {
        const float A = ta[u], B = ta[u+1], Cv = tb[u], D = tb[u+1];
        ev[2*u+0] = k11*A + k13*B + k31*Cv + k33*D;
        ev[2*u+1] = k10*A + k12*B + k30*Cv + k32*D;
        od[2*u+0] = k01*A + k03*B + k21*Cv + k23*D;
        od[2*u+1] = k00*A + k02*B + k20*Cv + k22*D;
    }

    float* s0 = &sm[w][0][0];
    float* s1 = &sm[w][1][0];
    ((float4*)s0)[2*lane    ] = make_float4(ev[0], ev[1], ev[2], ev[3]);
    ((float4*)s0)[2*lane + 1] = make_float4(ev[4], ev[5], ev[6], ev[7]);
    ((float4*)s1)[2*lane    ] = make_float4(od[0], od[1], od[2], od[3]);
    ((float4*)s1)[2*lane + 1] = make_float4(od[4], od[5], od[6], od[7]);
    __syncwarp();

    const long long obase = (long long)img * OH * OW;
    const long long r0off = obase + (long long)(2*i) * OW;
    const long long r1off = r0off + OW;
    const bool row1_ok = (2*i + 1) < OH;
    #pragma unroll
    for (int u = 0; u < 8; ++u) {
        const int c = lane + 32*u;
        if (c < OW) {
            if (r0off + c < n_out_elems)            out[r0off + c] = s0[c];
            if (row1_ok && r1off + c < n_out_elems) out[r1off + c] = s1[c];
        }
    }
}

extern "C" void kernel_launch(void* const* d_in, const int* in_sizes, int n_in,
                              void* d_out, int out_size)
{
    int imgs_idx = 0;
    for (int j = 1; j < n_in; ++j)
        if (in_sizes[j] > in_sizes[imgs_idx]) imgs_idx = j;
    const float* imgs = (const float*)d_in[imgs_idx];
    const float* ker  = nullptr;
    for (int j = 0; j < n_in; ++j)
        if (j != imgs_idx && in_sizes[j] >= 16 && in_sizes[j] < 1024) { ker = (const float*)d_in[j]; break; }

    const long long n_in_elems = (long long)in_sizes[imgs_idx];

    // Fast path: exact known shapes (2048 planes of 128x128 -> 255x255)
    if (n_in_elems == (long long)2048 * HB * WB &&
        out_size == 2048 * 255 * 255 && ker != nullptr) {
        blur_spec3<<<131072 / 8, 256>>>((const float4*)imgs, (const float4*)ker,
                                        (float*)d_out);
        return;
    }

    const long long planes = n_in_elems / (HB * WB);
    long long per_plane = (planes > 0) ? ((long long)out_size / planes) : 0;
    int ow = (int)(sqrt((double)per_plane) + 0.5);
    if (ow <= 0) ow = 2 * WB - 1;
    const int ntask = (int)(planes * HB);
    blur_generic<<<(ntask + 7) / 8, 256>>>(imgs, ker, (float*)d_out,
                                           ntask, n_in_elems, ow, ow, (long long)out_size);
}

// round 9
// speedup vs baseline: 1.0862x; 1.0862x over previous
#include <cuda_runtime.h>
#include <math.h>

// Blur_22754736735026: upfirdn2d, UP=2, DOWN=1, 4x4 kernel, pad (1,2).
// imgs: (16,128,128,128) f32 NCHW -> out: (16,128,255,255) f32.
//
// out(2i+py, 2j+px) = 2x2 weighted sum of in(i..i+1, j..j+1):
//   even out rows: kernel rows 1,3 ; odd rows: kernel rows 0,2
//   even out cols: kernel cols 1,3 ; odd cols: kernel cols 0,2
// Odd output row 2i+1 exists iff i < 127 (OH=255).
//
// Warp task = 4 input-row pairs: loads rows i0..i0+4 (5 LDG.128), emits
// output rows 2*i0 .. 2*i0+7. Stage each 2-row pair in smem (STS.128),
// drain with coalesced scalar STG (pitch 255 forbids vector stores).

#define HB   128
#define WB   128

// ---- one pair: rows X,Y -> out rows at g0, g0+255 (smem stage + drain) ----
__device__ __forceinline__ void do_pair(float* __restrict__ out,
                                        unsigned g0, bool row1_exists,
                                        const float4& X, float nX,
                                        const float4& Y, float nY,
                                        const float* kw,
                                        float* s0, float* s1, int lane)
{
    const float ta[5] = { X.x, X.y, X.z, X.w, nX };
    const float tb[5] = { Y.x, Y.y, Y.z, Y.w, nY };
    float ev[8], od[8];
    #pragma unroll
    for (int u = 0; u < 4; ++u) {
        const float A = ta[u], B = ta[u+1], Cv = tb[u], D = tb[u+1];
        ev[2*u+0] = kw[5]*A + kw[7]*B + kw[13]*Cv + kw[15]*D;  // k11,k13,k31,k33
        ev[2*u+1] = kw[4]*A + kw[6]*B + kw[12]*Cv + kw[14]*D;  // k10,k12,k30,k32
        od[2*u+0] = kw[1]*A + kw[3]*B + kw[ 9]*Cv + kw[11]*D;  // k01,k03,k21,k23
        od[2*u+1] = kw[0]*A + kw[2]*B + kw[ 8]*Cv + kw[10]*D;  // k00,k02,k20,k22
    }

    ((float4*)s0)[2*lane    ] = make_float4(ev[0], ev[1], ev[2], ev[3]);
    ((float4*)s0)[2*lane + 1] = make_float4(ev[4], ev[5], ev[6], ev[7]);
    ((float4*)s1)[2*lane    ] = make_float4(od[0], od[1], od[2], od[3]);
    ((float4*)s1)[2*lane + 1] = make_float4(od[4], od[5], od[6], od[7]);
    __syncwarp();

    const unsigned o1 = g0 + 255u;
    #pragma unroll
    for (int u = 0; u < 8; ++u) {
        const int c = lane + 32*u;
        if (u < 7 || lane < 31) {                  // c < 255
            out[g0 + c] = s0[c];
            if (row1_exists) out[o1 + c] = s1[c];
        }
    }
}

// ---------------- specialized: shapes known ---------------------------------
__global__ __launch_bounds__(256, 6)
void blur_spec4(const float4* __restrict__ in4,
                const float4* __restrict__ ker4,
                float* __restrict__ out)
{
    __shared__ float sm[8][4][256];                // 2 double-buffered row pairs

    const int lane = threadIdx.x & 31;
    const int w    = threadIdx.x >> 5;
    const unsigned task = blockIdx.x * 8u + w;     // 65536 tasks
    const unsigned t    = task & 31u;              // quad index in plane
    const unsigned img  = task >> 5;
    const unsigned i0   = 4u * t;                  // first input row

    float kw[16];
    {
        const float4 a = __ldg(ker4 + 0), b = __ldg(ker4 + 1),
                     c = __ldg(ker4 + 2), d = __ldg(ker4 + 3);
        kw[ 0]=a.x; kw[ 1]=a.y; kw[ 2]=a.z; kw[ 3]=a.w;
        kw[ 4]=b.x; kw[ 5]=b.y; kw[ 6]=b.z; kw[ 7]=b.w;
        kw[ 8]=c.x; kw[ 9]=c.y; kw[10]=c.z; kw[11]=c.w;
        kw[12]=d.x; kw[13]=d.y; kw[14]=d.z; kw[15]=d.w;
    }

    const unsigned rowbase = (img * HB + i0) * 32u + lane;
    const bool last = (t == 31u);                  // warp-uniform

    float4 r0 = in4[rowbase];
    float4 r1 = in4[rowbase + 32u];
    float4 r2 = in4[rowbase + 64u];
    float4 r3 = in4[rowbase + 96u];
    float4 r4 = make_float4(0.f, 0.f, 0.f, 0.f);
    if (!last) r4 = in4[rowbase + 128u];

    float n0 = __shfl_down_sync(0xffffffffu, r0.x, 1);
    float n1 = __shfl_down_sync(0xffffffffu, r1.x, 1);
    float n2 = __shfl_down_sync(0xffffffffu, r2.x, 1);
    float n3 = __shfl_down_sync(0xffffffffu, r3.x, 1);
    float n4 = __shfl_down_sync(0xffffffffu, r4.x, 1);
    if (lane == 31) { n0 = 0.f; n1 = 0.f; n2 = 0.f; n3 = 0.f; n4 = 0.f; }

    float* sA0 = &sm[w][0][0];
    float* sA1 = &sm[w][1][0];
    float* sB0 = &sm[w][2][0];
    float* sB1 = &sm[w][3][0];
    const unsigned g0 = img * 65025u + i0 * 510u;

    do_pair(out, g0,          true,  r0, n0, r1, n1, kw, sA0, sA1, lane);
    do_pair(out, g0 + 510u,   true,  r1, n1, r2, n2, kw, sB0, sB1, lane);
    __syncwarp();                                  // WAR on buffer A
    do_pair(out, g0 + 1020u,  true,  r2, n2, r3, n3, kw, sA0, sA1, lane);
    do_pair(out, g0 + 1530u, !last,  r3, n3, r4, n4, kw, sB0, sB1, lane);
}

// ---------------- generic guarded fallback (any shape) ----------------------
__global__ __launch_bounds__(256)
void blur_generic(const float* __restrict__ in,
                  const float* __restrict__ ker,
                  float* __restrict__ out,
                  int ntask, long long n_in_elems,
                  int OH, int OW, long long n_out_elems)
{
    __shared__ float sm[8][2][256];

    const int lane = threadIdx.x & 31;
    const int w    = threadIdx.x >> 5;
    const int task = blockIdx.x * 8 + w;
    if (task >= ntask) return;
    const int i    = task & (HB - 1);
    const int img  = task >> 7;

    float k00,k01,k02,k03,k10,k11,k12,k13,k20,k21,k22,k23,k30,k31,k32,k33;
    if (ker != nullptr) {
        k00 = __ldg(ker+ 0); k01 = __ldg(ker+ 1); k02 = __ldg(ker+ 2); k03 = __ldg(ker+ 3);
        k10 = __ldg(ker+ 4); k11 = __ldg(ker+ 5); k12 = __ldg(ker+ 6); k13 = __ldg(ker+ 7);
        k20 = __ldg(ker+ 8); k21 = __ldg(ker+ 9); k22 = __ldg(ker+10); k23 = __ldg(ker+11);
        k30 = __ldg(ker+12); k31 = __ldg(ker+13); k32 = __ldg(ker+14); k33 = __ldg(ker+15);
    } else {
        const float b0 = 0.125f, b1 = 0.375f;
        k00=b0*b0; k01=b0*b1; k02=b0*b1; k03=b0*b0;
        k10=b1*b0; k11=b1*b1; k12=b1*b1; k13=b1*b0;
        k20=b1*b0; k21=b1*b1; k22=b1*b1; k23=b1*b0;
        k30=b0*b0; k31=b0*b1; k32=b0*b1; k33=b0*b0;
    }

    const long long idx0 = ((long long)img * HB + i) * WB + lane * 4;
    float4 r0 = make_float4(0.f,0.f,0.f,0.f);
    float4 r1 = make_float4(0.f,0.f,0.f,0.f);
    if (idx0 + 3 < n_in_elems) r0 = *(const float4*)(in + idx0);
    if (i + 1 < HB && idx0 + WB + 3 < n_in_elems) r1 = *(const float4*)(in + idx0 + WB);

    float n0 = __shfl_down_sync(0xffffffffu, r0.x, 1);
    float n1 = __shfl_down_sync(0xffffffffu, r1.x, 1);
    if (lane == 31) { n0 = 0.f; n1 = 0.f; }

    const float ta[5] = { r0.x, r0.y, r0.z, r0.w, n0 };
    const float tb[5] = { r1.x, r1.y, r1.z, r1.w, n1 };

    float ev[8], od[8];
    #pragma unroll
    for (int u = 0; u < 4; ++u) {
        const float A = ta[u], B = ta[u+1], Cv = tb[u], D = tb[u+1];
        ev[2*u+0] = k11*A + k13*B + k31*Cv + k33*D;
        ev[2*u+1] = k10*A + k12*B + k30*Cv + k32*D;
        od[2*u+0] = k01*A + k03*B + k21*Cv + k23*D;
        od[2*u+1] = k00*A + k02*B + k20*Cv + k22*D;
    }

    float* s0 = &sm[w][0][0];
    float* s1 = &sm[w][1][0];
    ((float4*)s0)[2*lane    ] = make_float4(ev[0], ev[1], ev[2], ev[3]);
    ((float4*)s0)[2*lane + 1] = make_float4(ev[4], ev[5], ev[6], ev[7]);
    ((float4*)s1)[2*lane    ] = make_float4(od[0], od[1], od[2], od[3]);
    ((float4*)s1)[2*lane + 1] = make_float4(od[4], od[5], od[6], od[7]);
    __syncwarp();

    const long long obase = (long long)img * OH * OW;
    const long long r0off = obase + (long long)(2*i) * OW;
    const long long r1off = r0off + OW;
    const bool row1_ok = (2*i + 1) < OH;
    #pragma unroll
    for (int u = 0; u < 8; ++u) {
        const int c = lane + 32*u;
        if (c < OW) {
            if (r0off + c < n_out_elems)            out[r0off + c] = s0[c];
            if (row1_ok && r1off + c < n_out_elems) out[r1off + c] = s1[c];
        }
    }
}

extern "C" void kernel_launch(void* const* d_in, const int* in_sizes, int n_in,
                              void* d_out, int out_size)
{
    int imgs_idx = 0;
    for (int j = 1; j < n_in; ++j)
        if (in_sizes[j] > in_sizes[imgs_idx]) imgs_idx = j;
    const float* imgs = (const float*)d_in[imgs_idx];
    const float* ker  = nullptr;
    for (int j = 0; j < n_in; ++j)
        if (j != imgs_idx && in_sizes[j] >= 16 && in_sizes[j] < 1024) { ker = (const float*)d_in[j]; break; }

    const long long n_in_elems = (long long)in_sizes[imgs_idx];

    // Fast path: exact known shapes (2048 planes of 128x128 -> 255x255)
    if (n_in_elems == (long long)2048 * HB * WB &&
        out_size == 2048 * 255 * 255 && ker != nullptr) {
        // 2048 planes * 32 quad-tasks = 65536 tasks, 8 warps/block
        blur_spec4<<<65536 / 8, 256>>>((const float4*)imgs, (const float4*)ker,
                                       (float*)d_out);
        return;
    }

    const long long planes = n_in_elems / (HB * WB);
    long long per_plane = (planes > 0) ? ((long long)out_size / planes) : 0;
    int ow = (int)(sqrt((double)per_plane) + 0.5);
    if (ow <= 0) ow = 2 * WB - 1;
    const int ntask = (int)(planes * HB);
    blur_generic<<<(ntask + 7) / 8, 256>>>(imgs, ker, (float*)d_out,
                                           ntask, n_in_elems, ow, ow, (long long)out_size);
}